// round 8
// baseline (speedup 1.0000x reference)
#include <cuda_runtime.h>
#include <cuda_bf16.h>

// Problem constants (from reference)
#define BATCH 1024
#define DDIM  512
#define FDIM  4096

// out[b*D+d] = bias[d] + mask[b*D+d], vectorized float4, one-shot.
__global__ __launch_bounds__(256)
void tied_init_kernel(float4* __restrict__ out4,
                      const float4* __restrict__ bias4,
                      const float4* __restrict__ mask4,
                      int total4) {
    int i = blockIdx.x * blockDim.x + threadIdx.x;
    if (i >= total4) return;
    float4 m = mask4[i];
    float4 bv = __ldg(&bias4[i & (DDIM / 4 - 1)]);   // D/4 = 128, power of 2
    m.x += bv.x; m.y += bv.y; m.z += bv.z; m.w += bv.w;
    out4[i] = m;
}

// Process 4 packets (16 nnz) per thread as two front-batched halves of 8.
// Streams use __ldcs (read-once, evict-first) to keep L2 ways free for the
// atomic sector traffic. Scatter via fire-and-forget atomicAdd (REDG).
__device__ __forceinline__
void scatter8(const float4* __restrict__ vals4,
              const int4* __restrict__ b4,
              const int4* __restrict__ d4,
              const int4* __restrict__ f4,
              const float* __restrict__ w,
              float* __restrict__ out,
              int i, int j) {
    // ---- front-batched loads (8x LDG.128, streaming) ----
    float4 v0 = __ldcs(&vals4[i]);
    int4  bi0 = __ldcs(&b4[i]);
    int4  di0 = __ldcs(&d4[i]);
    int4  fi0 = __ldcs(&f4[i]);
    float4 v1 = __ldcs(&vals4[j]);
    int4  bi1 = __ldcs(&b4[j]);
    int4  di1 = __ldcs(&d4[j]);
    int4  fi1 = __ldcs(&f4[j]);

    float w00 = __ldg(&w[fi0.x]);
    float w01 = __ldg(&w[fi0.y]);
    float w02 = __ldg(&w[fi0.z]);
    float w03 = __ldg(&w[fi0.w]);
    float w10 = __ldg(&w[fi1.x]);
    float w11 = __ldg(&w[fi1.y]);
    float w12 = __ldg(&w[fi1.z]);
    float w13 = __ldg(&w[fi1.w]);

    atomicAdd(&out[bi0.x * DDIM + di0.x], v0.x * w00);
    atomicAdd(&out[bi0.y * DDIM + di0.y], v0.y * w01);
    atomicAdd(&out[bi0.z * DDIM + di0.z], v0.z * w02);
    atomicAdd(&out[bi0.w * DDIM + di0.w], v0.w * w03);
    atomicAdd(&out[bi1.x * DDIM + di1.x], v1.x * w10);
    atomicAdd(&out[bi1.y * DDIM + di1.y], v1.y * w11);
    atomicAdd(&out[bi1.z * DDIM + di1.z], v1.z * w12);
    atomicAdd(&out[bi1.w * DDIM + di1.w], v1.w * w13);
}

__global__ __launch_bounds__(256)
void tied_scatter_kernel(const float4* __restrict__ vals4,
                         const int4* __restrict__ b4,
                         const int4* __restrict__ d4,
                         const int4* __restrict__ f4,
                         const float* __restrict__ w,
                         float* __restrict__ out,
                         int n4) {
    const int PKT = 4 * 256;                    // packets per block
    const int blk = blockIdx.x * PKT;
    const int t = threadIdx.x;

    // Fast path: whole block in range (all but the last block).
    if (blk + PKT <= n4) {
        scatter8(vals4, b4, d4, f4, w, out, blk + t,           blk + t + 256);
        scatter8(vals4, b4, d4, f4, w, out, blk + t + 2 * 256, blk + t + 3 * 256);
        return;
    }

    // Slow path: last (partial) block.
    #pragma unroll
    for (int c = 0; c < 4; c++) {
        int i = blk + c * 256 + t;
        if (i < n4) {
            float4 v0 = __ldcs(&vals4[i]);
            int4  bi0 = __ldcs(&b4[i]);
            int4  di0 = __ldcs(&d4[i]);
            int4  fi0 = __ldcs(&f4[i]);
            atomicAdd(&out[bi0.x * DDIM + di0.x], v0.x * __ldg(&w[fi0.x]));
            atomicAdd(&out[bi0.y * DDIM + di0.y], v0.y * __ldg(&w[fi0.y]));
            atomicAdd(&out[bi0.z * DDIM + di0.z], v0.z * __ldg(&w[fi0.z]));
            atomicAdd(&out[bi0.w * DDIM + di0.w], v0.w * __ldg(&w[fi0.w]));
        }
    }
}

// Tail handler for NNZ not divisible by 4 (defensive; NNZ=10M is divisible).
__global__ __launch_bounds__(256)
void tied_scatter_tail_kernel(const float* __restrict__ vals,
                              const int* __restrict__ b,
                              const int* __restrict__ d,
                              const int* __restrict__ f,
                              const float* __restrict__ w,
                              float* __restrict__ out,
                              int start, int n) {
    int i = start + blockIdx.x * blockDim.x + threadIdx.x;
    if (i >= n) return;
    atomicAdd(&out[b[i] * DDIM + d[i]], vals[i] * __ldg(&w[f[i]]));
}

extern "C" void kernel_launch(void* const* d_in, const int* in_sizes, int n_in,
                              void* d_out, int out_size) {
    // metadata order: values, b_idx, d_idx, f_idx, weight, bias, mask
    const float* values = (const float*)d_in[0];
    const int*   b_idx  = (const int*)d_in[1];
    const int*   d_idx  = (const int*)d_in[2];
    const int*   f_idx  = (const int*)d_in[3];
    const float* weight = (const float*)d_in[4];
    const float* bias   = (const float*)d_in[5];
    const float* mask   = (const float*)d_in[6];
    float* out = (float*)d_out;

    const int nnz = in_sizes[0];
    const int THREADS = 256;

    // 1) init: out = bias + mask  (out_size = B*D = 524288, /4 = 131072)
    {
        int total4 = out_size / 4;
        int blocks = (total4 + THREADS - 1) / THREADS;   // 512 blocks
        tied_init_kernel<<<blocks, THREADS>>>((float4*)out,
                                              (const float4*)bias,
                                              (const float4*)mask,
                                              total4);
    }

    // 2) scatter: each block consumes 1024 4-nnz packets (4096 nnz)
    {
        int n4 = nnz / 4;
        int per_block = 4 * THREADS;                     // 1024 packets
        int blocks = (n4 + per_block - 1) / per_block;   // ~2442
        tied_scatter_kernel<<<blocks, THREADS>>>((const float4*)values,
                                                 (const int4*)b_idx,
                                                 (const int4*)d_idx,
                                                 (const int4*)f_idx,
                                                 weight, out, n4);
        int tail_start = n4 * 4;
        int tail = nnz - tail_start;
        if (tail > 0) {
            tied_scatter_tail_kernel<<<1, 256>>>(values, b_idx, d_idx, f_idx,
                                                 weight, out, tail_start, nnz);
        }
    }
}

// round 11
// speedup vs baseline: 1.0009x; 1.0009x over previous
#include <cuda_runtime.h>
#include <cuda_bf16.h>

// Problem constants (from reference)
#define BATCH 1024
#define DDIM  512
#define FDIM  4096

// out[b*D+d] = bias[d] + mask[b*D+d], vectorized float4, one-shot grid
// (512 blocks, no grid-stride loop) — measured 1.2us cheaper than the
// capped grid-stride variant.
__global__ __launch_bounds__(256)
void tied_init_kernel(float4* __restrict__ out4,
                      const float4* __restrict__ bias4,
                      const float4* __restrict__ mask4,
                      int total4) {
    int i = blockIdx.x * blockDim.x + threadIdx.x;
    if (i >= total4) return;
    float4 m = mask4[i];
    float4 bv = __ldg(&bias4[i & (DDIM / 4 - 1)]);   // D/4 = 128, power of 2
    m.x += bv.x; m.y += bv.y; m.z += bv.z; m.w += bv.w;
    out4[i] = m;
}

// Measured-best scatter config (65.8us): one-shot kernel, 8 nnz per thread
// (two float4/int4 chunks, all 8 LDG.128s front-batched), grid ~4883 blocks
// (~5 waves, hardware wave scheduling absorbs per-SM finish-time spread).
// Scatter via fire-and-forget atomicAdd (REDG) into the L2-resident output.
__global__ __launch_bounds__(256)
void tied_scatter_kernel(const float4* __restrict__ vals4,
                         const int4* __restrict__ b4,
                         const int4* __restrict__ d4,
                         const int4* __restrict__ f4,
                         const float* __restrict__ w,
                         float* __restrict__ out,
                         int n4) {
    const int base = blockIdx.x * (2 * 256) + threadIdx.x;
    const int i = base;            // chunk 0
    const int j = base + 256;      // chunk 1 (same block, +256: coalesced)

    // Fast path: whole block in range (true for all but the last block).
    if (blockIdx.x * (2 * 256) + 2 * 256 <= n4) {
        float4 v0 = vals4[i];
        int4  bi0 = b4[i];
        int4  di0 = d4[i];
        int4  fi0 = f4[i];
        float4 v1 = vals4[j];
        int4  bi1 = b4[j];
        int4  di1 = d4[j];
        int4  fi1 = f4[j];

        float w00 = __ldg(&w[fi0.x]);
        float w01 = __ldg(&w[fi0.y]);
        float w02 = __ldg(&w[fi0.z]);
        float w03 = __ldg(&w[fi0.w]);
        float w10 = __ldg(&w[fi1.x]);
        float w11 = __ldg(&w[fi1.y]);
        float w12 = __ldg(&w[fi1.z]);
        float w13 = __ldg(&w[fi1.w]);

        atomicAdd(&out[bi0.x * DDIM + di0.x], v0.x * w00);
        atomicAdd(&out[bi0.y * DDIM + di0.y], v0.y * w01);
        atomicAdd(&out[bi0.z * DDIM + di0.z], v0.z * w02);
        atomicAdd(&out[bi0.w * DDIM + di0.w], v0.w * w03);
        atomicAdd(&out[bi1.x * DDIM + di1.x], v1.x * w10);
        atomicAdd(&out[bi1.y * DDIM + di1.y], v1.y * w11);
        atomicAdd(&out[bi1.z * DDIM + di1.z], v1.z * w12);
        atomicAdd(&out[bi1.w * DDIM + di1.w], v1.w * w13);
        return;
    }

    // Slow path: last (partial) block only.
    if (i < n4) {
        float4 v0 = vals4[i];
        int4  bi0 = b4[i];
        int4  di0 = d4[i];
        int4  fi0 = f4[i];
        atomicAdd(&out[bi0.x * DDIM + di0.x], v0.x * __ldg(&w[fi0.x]));
        atomicAdd(&out[bi0.y * DDIM + di0.y], v0.y * __ldg(&w[fi0.y]));
        atomicAdd(&out[bi0.z * DDIM + di0.z], v0.z * __ldg(&w[fi0.z]));
        atomicAdd(&out[bi0.w * DDIM + di0.w], v0.w * __ldg(&w[fi0.w]));
    }
    if (j < n4) {
        float4 v1 = vals4[j];
        int4  bi1 = b4[j];
        int4  di1 = d4[j];
        int4  fi1 = f4[j];
        atomicAdd(&out[bi1.x * DDIM + di1.x], v1.x * __ldg(&w[fi1.x]));
        atomicAdd(&out[bi1.y * DDIM + di1.y], v1.y * __ldg(&w[fi1.y]));
        atomicAdd(&out[bi1.z * DDIM + di1.z], v1.z * __ldg(&w[fi1.z]));
        atomicAdd(&out[bi1.w * DDIM + di1.w], v1.w * __ldg(&w[fi1.w]));
    }
}

// Tail handler for NNZ not divisible by 4 (defensive; NNZ=10M is divisible,
// so this never launches in practice).
__global__ __launch_bounds__(256)
void tied_scatter_tail_kernel(const float* __restrict__ vals,
                              const int* __restrict__ b,
                              const int* __restrict__ d,
                              const int* __restrict__ f,
                              const float* __restrict__ w,
                              float* __restrict__ out,
                              int start, int n) {
    int i = start + blockIdx.x * blockDim.x + threadIdx.x;
    if (i >= n) return;
    atomicAdd(&out[b[i] * DDIM + d[i]], vals[i] * __ldg(&w[f[i]]));
}

extern "C" void kernel_launch(void* const* d_in, const int* in_sizes, int n_in,
                              void* d_out, int out_size) {
    // metadata order: values, b_idx, d_idx, f_idx, weight, bias, mask
    const float* values = (const float*)d_in[0];
    const int*   b_idx  = (const int*)d_in[1];
    const int*   d_idx  = (const int*)d_in[2];
    const int*   f_idx  = (const int*)d_in[3];
    const float* weight = (const float*)d_in[4];
    const float* bias   = (const float*)d_in[5];
    const float* mask   = (const float*)d_in[6];
    float* out = (float*)d_out;

    const int nnz = in_sizes[0];
    const int THREADS = 256;

    // 1) init: out = bias + mask  (out_size = B*D = 524288, /4 = 131072)
    {
        int total4 = out_size / 4;
        int blocks = (total4 + THREADS - 1) / THREADS;   // 512 blocks, one-shot
        tied_init_kernel<<<blocks, THREADS>>>((float4*)out,
                                              (const float4*)bias,
                                              (const float4*)mask,
                                              total4);
    }

    // 2) scatter: each block consumes 512 4-nnz packets (2048 nnz)
    {
        int n4 = nnz / 4;
        int per_block = 2 * THREADS;                     // 512 packets
        int blocks = (n4 + per_block - 1) / per_block;   // ~4883
        tied_scatter_kernel<<<blocks, THREADS>>>((const float4*)values,
                                                 (const int4*)b_idx,
                                                 (const int4*)d_idx,
                                                 (const int4*)f_idx,
                                                 weight, out, n4);
        int tail_start = n4 * 4;
        int tail = nnz - tail_start;
        if (tail > 0) {
            tied_scatter_tail_kernel<<<1, 256>>>(values, b_idx, d_idx, f_idx,
                                                 weight, out, tail_start, nnz);
        }
    }
}

// round 12
// speedup vs baseline: 1.0014x; 1.0005x over previous
#include <cuda_runtime.h>
#include <cuda_bf16.h>

// Problem constants (from reference)
#define BATCH 1024
#define DDIM  512
#define FDIM  4096

// out[b*D+d] = bias[d] + mask[b*D+d], vectorized float4, one-shot grid.
// Calls cudaTriggerProgrammaticLaunchCompletion() at entry so the PDL-linked
// scatter kernel can launch immediately and overlap its load prologue with
// this kernel's memory traffic.
__global__ __launch_bounds__(256)
void tied_init_kernel(float4* __restrict__ out4,
                      const float4* __restrict__ bias4,
                      const float4* __restrict__ mask4,
                      int total4) {
#if __CUDA_ARCH__ >= 900
    cudaTriggerProgrammaticLaunchCompletion();
#endif
    int i = blockIdx.x * blockDim.x + threadIdx.x;
    if (i >= total4) return;
    float4 m = mask4[i];
    float4 bv = __ldg(&bias4[i & (DDIM / 4 - 1)]);   // D/4 = 128, power of 2
    m.x += bv.x; m.y += bv.y; m.z += bv.z; m.w += bv.w;
    out4[i] = m;
}

// Measured-best scatter config (65.8us stable across runs): one-shot kernel,
// 8 nnz per thread (two float4/int4 chunks, 8 LDG.128s front-batched), grid
// ~4883 blocks. PDL: all loads + weight gathers + products are issued BEFORE
// cudaGridDependencySynchronize(); only the atomics (which touch `out`,
// written by init) wait for the init grid to complete.
__global__ __launch_bounds__(256)
void tied_scatter_kernel(const float4* __restrict__ vals4,
                         const int4* __restrict__ b4,
                         const int4* __restrict__ d4,
                         const int4* __restrict__ f4,
                         const float* __restrict__ w,
                         float* __restrict__ out,
                         int n4) {
    const int base = blockIdx.x * (2 * 256) + threadIdx.x;
    const int i = base;            // chunk 0
    const int j = base + 256;      // chunk 1 (same block, +256: coalesced)

    // Fast path: whole block in range (true for all but the last block).
    if (blockIdx.x * (2 * 256) + 2 * 256 <= n4) {
        float4 v0 = vals4[i];
        int4  bi0 = b4[i];
        int4  di0 = d4[i];
        int4  fi0 = f4[i];
        float4 v1 = vals4[j];
        int4  bi1 = b4[j];
        int4  di1 = d4[j];
        int4  fi1 = f4[j];

        float w00 = __ldg(&w[fi0.x]);
        float w01 = __ldg(&w[fi0.y]);
        float w02 = __ldg(&w[fi0.z]);
        float w03 = __ldg(&w[fi0.w]);
        float w10 = __ldg(&w[fi1.x]);
        float w11 = __ldg(&w[fi1.y]);
        float w12 = __ldg(&w[fi1.z]);
        float w13 = __ldg(&w[fi1.w]);

        float c00 = v0.x * w00;
        float c01 = v0.y * w01;
        float c02 = v0.z * w02;
        float c03 = v0.w * w03;
        float c10 = v1.x * w10;
        float c11 = v1.y * w11;
        float c12 = v1.z * w12;
        float c13 = v1.w * w13;

#if __CUDA_ARCH__ >= 900
        cudaGridDependencySynchronize();   // init grid's writes now visible
#endif

        atomicAdd(&out[bi0.x * DDIM + di0.x], c00);
        atomicAdd(&out[bi0.y * DDIM + di0.y], c01);
        atomicAdd(&out[bi0.z * DDIM + di0.z], c02);
        atomicAdd(&out[bi0.w * DDIM + di0.w], c03);
        atomicAdd(&out[bi1.x * DDIM + di1.x], c10);
        atomicAdd(&out[bi1.y * DDIM + di1.y], c11);
        atomicAdd(&out[bi1.z * DDIM + di1.z], c12);
        atomicAdd(&out[bi1.w * DDIM + di1.w], c13);
        return;
    }

    // Slow path: last (partial) block only.
#if __CUDA_ARCH__ >= 900
    cudaGridDependencySynchronize();
#endif
    if (i < n4) {
        float4 v0 = vals4[i];
        int4  bi0 = b4[i];
        int4  di0 = d4[i];
        int4  fi0 = f4[i];
        atomicAdd(&out[bi0.x * DDIM + di0.x], v0.x * __ldg(&w[fi0.x]));
        atomicAdd(&out[bi0.y * DDIM + di0.y], v0.y * __ldg(&w[fi0.y]));
        atomicAdd(&out[bi0.z * DDIM + di0.z], v0.z * __ldg(&w[fi0.z]));
        atomicAdd(&out[bi0.w * DDIM + di0.w], v0.w * __ldg(&w[fi0.w]));
    }
    if (j < n4) {
        float4 v1 = vals4[j];
        int4  bi1 = b4[j];
        int4  di1 = d4[j];
        int4  fi1 = f4[j];
        atomicAdd(&out[bi1.x * DDIM + di1.x], v1.x * __ldg(&w[fi1.x]));
        atomicAdd(&out[bi1.y * DDIM + di1.y], v1.y * __ldg(&w[fi1.y]));
        atomicAdd(&out[bi1.z * DDIM + di1.z], v1.z * __ldg(&w[fi1.z]));
        atomicAdd(&out[bi1.w * DDIM + di1.w], v1.w * __ldg(&w[fi1.w]));
    }
}

// Tail handler for NNZ not divisible by 4 (defensive; NNZ=10M is divisible,
// so this never launches in practice).
__global__ __launch_bounds__(256)
void tied_scatter_tail_kernel(const float* __restrict__ vals,
                              const int* __restrict__ b,
                              const int* __restrict__ d,
                              const int* __restrict__ f,
                              const float* __restrict__ w,
                              float* __restrict__ out,
                              int start, int n) {
    int i = start + blockIdx.x * blockDim.x + threadIdx.x;
    if (i >= n) return;
    atomicAdd(&out[b[i] * DDIM + d[i]], vals[i] * __ldg(&w[f[i]]));
}

extern "C" void kernel_launch(void* const* d_in, const int* in_sizes, int n_in,
                              void* d_out, int out_size) {
    // metadata order: values, b_idx, d_idx, f_idx, weight, bias, mask
    const float* values = (const float*)d_in[0];
    const int*   b_idx  = (const int*)d_in[1];
    const int*   d_idx  = (const int*)d_in[2];
    const int*   f_idx  = (const int*)d_in[3];
    const float* weight = (const float*)d_in[4];
    const float* bias   = (const float*)d_in[5];
    const float* mask   = (const float*)d_in[6];
    float* out = (float*)d_out;

    const int nnz = in_sizes[0];
    const int THREADS = 256;

    // 1) init: out = bias + mask  (out_size = B*D = 524288, /4 = 131072)
    {
        int total4 = out_size / 4;
        int blocks = (total4 + THREADS - 1) / THREADS;   // 512 blocks, one-shot
        tied_init_kernel<<<blocks, THREADS>>>((float4*)out,
                                              (const float4*)bias,
                                              (const float4*)mask,
                                              total4);
    }

    // 2) scatter, PDL-linked to init: launches immediately, loads overlap
    //    init's tail; atomics wait via cudaGridDependencySynchronize().
    {
        int n4 = nnz / 4;
        int per_block = 2 * THREADS;                     // 512 packets
        int blocks = (n4 + per_block - 1) / per_block;   // ~4883

        cudaLaunchConfig_t cfg = {};
        cfg.gridDim = dim3((unsigned)blocks, 1, 1);
        cfg.blockDim = dim3(THREADS, 1, 1);
        cfg.dynamicSmemBytes = 0;
        cfg.stream = 0;
        cudaLaunchAttribute attrs[1];
        attrs[0].id = cudaLaunchAttributeProgrammaticStreamSerialization;
        attrs[0].val.programmaticStreamSerializationAllowed = 1;
        cfg.attrs = attrs;
        cfg.numAttrs = 1;

        cudaLaunchKernelEx(&cfg, tied_scatter_kernel,
                           (const float4*)values,
                           (const int4*)b_idx,
                           (const int4*)d_idx,
                           (const int4*)f_idx,
                           weight, out, n4);

        int tail_start = n4 * 4;
        int tail = nnz - tail_start;
        if (tail > 0) {
            tied_scatter_tail_kernel<<<1, 256>>>(values, b_idx, d_idx, f_idx,
                                                 weight, out, tail_start, nnz);
        }
    }
}